// round 15
// baseline (speedup 1.0000x reference)
#include <cuda_runtime.h>
#include <cuda_bf16.h>
#include <math.h>

// ---------------- problem constants ----------------
#define T_MAX   4096          // B*L tokens
#define D_DIM   1024
#define E_NUM   8
#define F_DIM   2048
#define TWO_F   4096
#define NP      (T_MAX * 2)   // total (token, k) pairs, always exactly 2*T

#define BM 128
#define BN 128
#define BK 8
#define SSTRIDE 132           // padded smem row stride (multiple of 4, bank-rotating)
#define MAX_TILES 96

// ---------------- device scratch (static, no allocations) ----------------
__device__ int    g_cnt[E_NUM];
__device__ int    g_cursor[E_NUM];
__device__ int    g_off[E_NUM + 1];
__device__ int    g_num_tiles;
__device__ int    g_tile_expert[MAX_TILES];
__device__ int    g_tile_row0[MAX_TILES];
__device__ int    g_tile_m[MAX_TILES];
__device__ int2   g_sel[T_MAX];
__device__ float2 g_wts[T_MAX];
__device__ int    g_pair_tok[NP];
__device__ float  g_pair_w[NP];
__device__ float  g_H[(size_t)NP * F_DIM];   // 64 MiB activation scratch

// ---------------- helpers ----------------
__device__ __forceinline__ float act_swiglu(float g, float v) {
    g = fminf(g, 9.0f);
    v = fminf(fmaxf(v, -9.0f), 9.0f);
    float s = 1.0f / (1.0f + expf(-1.702f * g));
    return g * s * (v + 1.0f);
}

// ---------------- kernel 0: reset counters ----------------
__global__ void init_kernel() {
    int i = threadIdx.x;
    if (i < E_NUM) { g_cnt[i] = 0; g_cursor[i] = 0; }
}

// ---------------- kernel 1: gate = x @ gate_w, top2, softmax ----------------
// one warp per token
__global__ void gate_kernel(const float* __restrict__ x,
                            const float* __restrict__ gw, int T) {
    int gwarp = (blockIdx.x * blockDim.x + threadIdx.x) >> 5;
    int lane  = threadIdx.x & 31;
    if (gwarp >= T) return;
    const float* xr = x + (size_t)gwarp * D_DIM;

    float acc[8] = {0,0,0,0,0,0,0,0};
    for (int d = lane; d < D_DIM; d += 32) {
        float xv = xr[d];
        float4 w0 = *(const float4*)(gw + (size_t)d * E_NUM);
        float4 w1 = *(const float4*)(gw + (size_t)d * E_NUM + 4);
        acc[0] = fmaf(xv, w0.x, acc[0]);
        acc[1] = fmaf(xv, w0.y, acc[1]);
        acc[2] = fmaf(xv, w0.z, acc[2]);
        acc[3] = fmaf(xv, w0.w, acc[3]);
        acc[4] = fmaf(xv, w1.x, acc[4]);
        acc[5] = fmaf(xv, w1.y, acc[5]);
        acc[6] = fmaf(xv, w1.z, acc[6]);
        acc[7] = fmaf(xv, w1.w, acc[7]);
    }
    #pragma unroll
    for (int e = 0; e < 8; e++) {
        #pragma unroll
        for (int o = 16; o > 0; o >>= 1)
            acc[e] += __shfl_xor_sync(0xFFFFFFFFu, acc[e], o);
    }
    if (lane == 0) {
        float v0 = -INFINITY, v1 = -INFINITY;
        int   i0 = 0,          i1 = 0;
        #pragma unroll
        for (int e = 0; e < 8; e++) {
            float v = acc[e];
            if (v > v0)      { v1 = v0; i1 = i0; v0 = v; i0 = e; }
            else if (v > v1) { v1 = v;  i1 = e; }
        }
        // softmax over {v0, v1}; v0 is the max
        float e1 = expf(v1 - v0);
        float inv = 1.0f / (1.0f + e1);
        g_sel[gwarp] = make_int2(i0, i1);
        g_wts[gwarp] = make_float2(inv, e1 * inv);
        atomicAdd(&g_cnt[i0], 1);
        atomicAdd(&g_cnt[i1], 1);
    }
}

// ---------------- kernel 2: prefix offsets + tile map ----------------
__global__ void setup_kernel() {
    if (threadIdx.x == 0 && blockIdx.x == 0) {
        int off = 0, nt = 0;
        for (int e = 0; e < E_NUM; e++) {
            g_off[e] = off;
            int c = g_cnt[e];
            for (int m = 0; m < c; m += BM) {
                g_tile_expert[nt] = e;
                g_tile_row0[nt]   = off + m;
                g_tile_m[nt]      = min(BM, c - m);
                nt++;
            }
            off += c;
        }
        g_off[E_NUM] = off;
        g_num_tiles  = nt;
    }
}

// ---------------- kernel 3: scatter tokens into expert-sorted pair list ----
__global__ void scatter_kernel(int T) {
    int t = blockIdx.x * blockDim.x + threadIdx.x;
    if (t >= T) return;
    int2   sel = g_sel[t];
    float2 w   = g_wts[t];
    int p0 = g_off[sel.x] + atomicAdd(&g_cursor[sel.x], 1);
    g_pair_tok[p0] = t;  g_pair_w[p0] = w.x;
    int p1 = g_off[sel.y] + atomicAdd(&g_cursor[sel.y], 1);
    g_pair_tok[p1] = t;  g_pair_w[p1] = w.y;
}

// ---------------- kernel 4: H = swiglu(x_gathered @ d1w[e]^T + b1) ----------
// C[p][c] = sum_d x[tok(p)][d] * d1w[e][c][d]   (both K-major -> A*B^T)
__global__ __launch_bounds__(256)
void gemm1_kernel(const float* __restrict__ x,
                  const float* __restrict__ d1w,
                  const float* __restrict__ d1b) {
    int tile = blockIdx.y;
    if (tile >= g_num_tiles) return;
    int e     = g_tile_expert[tile];
    int row0  = g_tile_row0[tile];
    int mrows = g_tile_m[tile];
    int n0    = blockIdx.x * BN;

    __shared__ float As[BK][SSTRIDE];
    __shared__ float Bs[BK][SSTRIDE];

    int tid = threadIdx.x;
    int r   = tid >> 1;          // 0..127
    int kk  = (tid & 1) * 4;     // 0 or 4

    int tokr = g_pair_tok[row0 + ((r < mrows) ? r : 0)];
    const float* arow = x   + (size_t)tokr * D_DIM;
    const float* brow = d1w + ((size_t)e * TWO_F + (n0 + r)) * D_DIM;

    int tx = tid & 15, ty = tid >> 4;
    int ry0 = ty * 4, ry1 = ty * 4 + 64;
    int cx0 = tx * 4, cx1 = tx * 4 + 64;

    float acc[8][8];
    #pragma unroll
    for (int i = 0; i < 8; i++)
        #pragma unroll
        for (int j = 0; j < 8; j++) acc[i][j] = 0.0f;

    for (int k0 = 0; k0 < D_DIM; k0 += BK) {
        float4 a4 = *(const float4*)(arow + k0 + kk);
        float4 b4 = *(const float4*)(brow + k0 + kk);
        __syncthreads();
        As[kk+0][r] = a4.x; As[kk+1][r] = a4.y; As[kk+2][r] = a4.z; As[kk+3][r] = a4.w;
        Bs[kk+0][r] = b4.x; Bs[kk+1][r] = b4.y; Bs[kk+2][r] = b4.z; Bs[kk+3][r] = b4.w;
        __syncthreads();
        #pragma unroll
        for (int k = 0; k < BK; k++) {
            float4 a0 = *(const float4*)&As[k][ry0];
            float4 a1 = *(const float4*)&As[k][ry1];
            float4 b0 = *(const float4*)&Bs[k][cx0];
            float4 b1 = *(const float4*)&Bs[k][cx1];
            float av[8] = {a0.x,a0.y,a0.z,a0.w,a1.x,a1.y,a1.z,a1.w};
            float bv[8] = {b0.x,b0.y,b0.z,b0.w,b1.x,b1.y,b1.z,b1.w};
            #pragma unroll
            for (int i = 0; i < 8; i++)
                #pragma unroll
                for (int j = 0; j < 8; j++)
                    acc[i][j] = fmaf(av[i], bv[j], acc[i][j]);
        }
    }

    // epilogue: bias + swiglu on (g,v) pairs, store to g_H
    const float* b1e = d1b + (size_t)e * TWO_F;
    float4 bias0 = *(const float4*)(b1e + n0 + cx0);
    float4 bias1 = *(const float4*)(b1e + n0 + cx1);
    int fbase = (n0 >> 1) + tx * 2;
    #pragma unroll
    for (int i = 0; i < 8; i++) {
        int rl = (i < 4) ? (ry0 + i) : (ry1 + i - 4);
        if (rl >= mrows) continue;
        float* Hrow = g_H + (size_t)(row0 + rl) * F_DIM;
        float2 h0, h1;
        h0.x = act_swiglu(acc[i][0] + bias0.x, acc[i][1] + bias0.y);
        h0.y = act_swiglu(acc[i][2] + bias0.z, acc[i][3] + bias0.w);
        h1.x = act_swiglu(acc[i][4] + bias1.x, acc[i][5] + bias1.y);
        h1.y = act_swiglu(acc[i][6] + bias1.z, acc[i][7] + bias1.w);
        *(float2*)(Hrow + fbase)      = h0;
        *(float2*)(Hrow + fbase + 32) = h1;
    }
}

// ---------------- kernel 5: y = H @ d2w[e]^T + b2 ; out += w * y -----------
// C[p][d] = sum_f H[p][f] * d2w[e][d][f]
__global__ __launch_bounds__(256)
void gemm2_kernel(const float* __restrict__ d2w,
                  const float* __restrict__ d2b,
                  float* __restrict__ out) {
    int tile = blockIdx.y;
    if (tile >= g_num_tiles) return;
    int e     = g_tile_expert[tile];
    int row0  = g_tile_row0[tile];
    int mrows = g_tile_m[tile];
    int n0    = blockIdx.x * BN;

    __shared__ float As[BK][SSTRIDE];
    __shared__ float Bs[BK][SSTRIDE];

    int tid = threadIdx.x;
    int r   = tid >> 1;
    int kk  = (tid & 1) * 4;

    int ra = (r < mrows) ? r : 0;
    const float* arow = g_H + (size_t)(row0 + ra) * F_DIM;
    const float* brow = d2w + ((size_t)e * D_DIM + (n0 + r)) * F_DIM;

    int tx = tid & 15, ty = tid >> 4;
    int ry0 = ty * 4, ry1 = ty * 4 + 64;
    int cx0 = tx * 4, cx1 = tx * 4 + 64;

    float acc[8][8];
    #pragma unroll
    for (int i = 0; i < 8; i++)
        #pragma unroll
        for (int j = 0; j < 8; j++) acc[i][j] = 0.0f;

    for (int k0 = 0; k0 < F_DIM; k0 += BK) {
        float4 a4 = *(const float4*)(arow + k0 + kk);
        float4 b4 = *(const float4*)(brow + k0 + kk);
        __syncthreads();
        As[kk+0][r] = a4.x; As[kk+1][r] = a4.y; As[kk+2][r] = a4.z; As[kk+3][r] = a4.w;
        Bs[kk+0][r] = b4.x; Bs[kk+1][r] = b4.y; Bs[kk+2][r] = b4.z; Bs[kk+3][r] = b4.w;
        __syncthreads();
        #pragma unroll
        for (int k = 0; k < BK; k++) {
            float4 a0 = *(const float4*)&As[k][ry0];
            float4 a1 = *(const float4*)&As[k][ry1];
            float4 b0 = *(const float4*)&Bs[k][cx0];
            float4 b1 = *(const float4*)&Bs[k][cx1];
            float av[8] = {a0.x,a0.y,a0.z,a0.w,a1.x,a1.y,a1.z,a1.w};
            float bv[8] = {b0.x,b0.y,b0.z,b0.w,b1.x,b1.y,b1.z,b1.w};
            #pragma unroll
            for (int i = 0; i < 8; i++)
                #pragma unroll
                for (int j = 0; j < 8; j++)
                    acc[i][j] = fmaf(av[i], bv[j], acc[i][j]);
        }
    }

    // epilogue: bias, weight, atomic scatter-add into out[token]
    const float* b2e = d2b + (size_t)e * D_DIM;
    float4 bias0 = *(const float4*)(b2e + n0 + cx0);
    float4 bias1 = *(const float4*)(b2e + n0 + cx1);
    float bv0[8] = {bias0.x,bias0.y,bias0.z,bias0.w,bias1.x,bias1.y,bias1.z,bias1.w};
    #pragma unroll
    for (int i = 0; i < 8; i++) {
        int rl = (i < 4) ? (ry0 + i) : (ry1 + i - 4);
        if (rl >= mrows) continue;
        int p = row0 + rl;
        int tok   = g_pair_tok[p];
        float wgt = g_pair_w[p];
        float* orow = out + (size_t)tok * D_DIM;
        #pragma unroll
        for (int j = 0; j < 8; j++) {
            int d = n0 + ((j < 4) ? (cx0 + j) : (cx1 + j - 4));
            atomicAdd(orow + d, wgt * (acc[i][j] + bv0[j]));
        }
    }
}

// ---------------- launch ----------------
extern "C" void kernel_launch(void* const* d_in, const int* in_sizes, int n_in,
                              void* d_out, int out_size) {
    const float* x   = (const float*)d_in[0];
    const float* gw  = (const float*)d_in[1];
    const float* d1w = (const float*)d_in[2];
    const float* d1b = (const float*)d_in[3];
    const float* d2w = (const float*)d_in[4];
    const float* d2b = (const float*)d_in[5];
    float* out = (float*)d_out;

    int T = in_sizes[0] / D_DIM;   // 4096

    cudaMemsetAsync(d_out, 0, (size_t)out_size * sizeof(float));
    init_kernel<<<1, 32>>>();
    gate_kernel<<<(T + 7) / 8, 256>>>(x, gw, T);
    setup_kernel<<<1, 32>>>();
    scatter_kernel<<<(T + 255) / 256, 256>>>(T);

    dim3 grid1(TWO_F / BN, MAX_TILES);   // (32, 96)
    gemm1_kernel<<<grid1, 256>>>(x, d1w, d1b);

    dim3 grid2(D_DIM / BN, MAX_TILES);   // (8, 96)
    gemm2_kernel<<<grid2, 256>>>(d2w, d2b, out);
}

// round 16
// speedup vs baseline: 1.0011x; 1.0011x over previous
#include <cuda_runtime.h>
#include <cuda_bf16.h>
#include <math.h>

// ---------------- problem constants ----------------
#define T_MAX   4096          // B*L tokens
#define D_DIM   1024
#define E_NUM   8
#define F_DIM   2048
#define TWO_F   4096
#define NP      (T_MAX * 2)   // total (token, k) pairs, always exactly 2*T

#define BM 128
#define BN 128
#define BK 8
#define SSTRIDE 132           // padded smem row stride (multiple of 4, bank-rotating)
#define MAX_TILES 96

// ---------------- device scratch (static, no allocations) ----------------
__device__ int    g_cnt[E_NUM];
__device__ int    g_cursor[E_NUM];
__device__ int    g_off[E_NUM + 1];
__device__ int    g_num_tiles;
__device__ int    g_tile_expert[MAX_TILES];
__device__ int    g_tile_row0[MAX_TILES];
__device__ int    g_tile_m[MAX_TILES];
__device__ int2   g_sel[T_MAX];
__device__ float2 g_wts[T_MAX];
__device__ int    g_pair_tok[NP];
__device__ float  g_pair_w[NP];
__device__ float  g_H[(size_t)NP * F_DIM];   // 64 MiB activation scratch

// ---------------- helpers ----------------
__device__ __forceinline__ float act_swiglu(float g, float v) {
    g = fminf(g, 9.0f);
    v = fminf(fmaxf(v, -9.0f), 9.0f);
    float s = 1.0f / (1.0f + expf(-1.702f * g));
    return g * s * (v + 1.0f);
}

// ---------------- kernel 0: reset counters ----------------
__global__ void init_kernel() {
    int i = threadIdx.x;
    if (i < E_NUM) { g_cnt[i] = 0; g_cursor[i] = 0; }
}

// ---------------- kernel 1: gate = x @ gate_w, top2, softmax ----------------
// one warp per token
__global__ void gate_kernel(const float* __restrict__ x,
                            const float* __restrict__ gw, int T) {
    int gwarp = (blockIdx.x * blockDim.x + threadIdx.x) >> 5;
    int lane  = threadIdx.x & 31;
    if (gwarp >= T) return;
    const float* xr = x + (size_t)gwarp * D_DIM;

    float acc[8] = {0,0,0,0,0,0,0,0};
    for (int d = lane; d < D_DIM; d += 32) {
        float xv = xr[d];
        float4 w0 = *(const float4*)(gw + (size_t)d * E_NUM);
        float4 w1 = *(const float4*)(gw + (size_t)d * E_NUM + 4);
        acc[0] = fmaf(xv, w0.x, acc[0]);
        acc[1] = fmaf(xv, w0.y, acc[1]);
        acc[2] = fmaf(xv, w0.z, acc[2]);
        acc[3] = fmaf(xv, w0.w, acc[3]);
        acc[4] = fmaf(xv, w1.x, acc[4]);
        acc[5] = fmaf(xv, w1.y, acc[5]);
        acc[6] = fmaf(xv, w1.z, acc[6]);
        acc[7] = fmaf(xv, w1.w, acc[7]);
    }
    #pragma unroll
    for (int e = 0; e < 8; e++) {
        #pragma unroll
        for (int o = 16; o > 0; o >>= 1)
            acc[e] += __shfl_xor_sync(0xFFFFFFFFu, acc[e], o);
    }
    if (lane == 0) {
        float v0 = -INFINITY, v1 = -INFINITY;
        int   i0 = 0,          i1 = 0;
        #pragma unroll
        for (int e = 0; e < 8; e++) {
            float v = acc[e];
            if (v > v0)      { v1 = v0; i1 = i0; v0 = v; i0 = e; }
            else if (v > v1) { v1 = v;  i1 = e; }
        }
        // softmax over {v0, v1}; v0 is the max
        float e1 = expf(v1 - v0);
        float inv = 1.0f / (1.0f + e1);
        g_sel[gwarp] = make_int2(i0, i1);
        g_wts[gwarp] = make_float2(inv, e1 * inv);
        atomicAdd(&g_cnt[i0], 1);
        atomicAdd(&g_cnt[i1], 1);
    }
}

// ---------------- kernel 2: prefix offsets + tile map ----------------
__global__ void setup_kernel() {
    if (threadIdx.x == 0 && blockIdx.x == 0) {
        int off = 0, nt = 0;
        for (int e = 0; e < E_NUM; e++) {
            g_off[e] = off;
            int c = g_cnt[e];
            for (int m = 0; m < c; m += BM) {
                g_tile_expert[nt] = e;
                g_tile_row0[nt]   = off + m;
                g_tile_m[nt]      = min(BM, c - m);
                nt++;
            }
            off += c;
        }
        g_off[E_NUM] = off;
        g_num_tiles  = nt;
    }
}

// ---------------- kernel 3: scatter tokens into expert-sorted pair list ----
__global__ void scatter_kernel(int T) {
    int t = blockIdx.x * blockDim.x + threadIdx.x;
    if (t >= T) return;
    int2   sel = g_sel[t];
    float2 w   = g_wts[t];
    int p0 = g_off[sel.x] + atomicAdd(&g_cursor[sel.x], 1);
    g_pair_tok[p0] = t;  g_pair_w[p0] = w.x;
    int p1 = g_off[sel.y] + atomicAdd(&g_cursor[sel.y], 1);
    g_pair_tok[p1] = t;  g_pair_w[p1] = w.y;
}

// ---------------- kernel 4: H = swiglu(x_gathered @ d1w[e]^T + b1) ----------
// C[p][c] = sum_d x[tok(p)][d] * d1w[e][c][d]   (both K-major -> A*B^T)
__global__ __launch_bounds__(256)
void gemm1_kernel(const float* __restrict__ x,
                  const float* __restrict__ d1w,
                  const float* __restrict__ d1b) {
    int tile = blockIdx.y;
    if (tile >= g_num_tiles) return;
    int e     = g_tile_expert[tile];
    int row0  = g_tile_row0[tile];
    int mrows = g_tile_m[tile];
    int n0    = blockIdx.x * BN;

    __shared__ float As[BK][SSTRIDE];
    __shared__ float Bs[BK][SSTRIDE];

    int tid = threadIdx.x;
    int r   = tid >> 1;          // 0..127
    int kk  = (tid & 1) * 4;     // 0 or 4

    int tokr = g_pair_tok[row0 + ((r < mrows) ? r : 0)];
    const float* arow = x   + (size_t)tokr * D_DIM;
    const float* brow = d1w + ((size_t)e * TWO_F + (n0 + r)) * D_DIM;

    int tx = tid & 15, ty = tid >> 4;
    int ry0 = ty * 4, ry1 = ty * 4 + 64;
    int cx0 = tx * 4, cx1 = tx * 4 + 64;

    float acc[8][8];
    #pragma unroll
    for (int i = 0; i < 8; i++)
        #pragma unroll
        for (int j = 0; j < 8; j++) acc[i][j] = 0.0f;

    for (int k0 = 0; k0 < D_DIM; k0 += BK) {
        float4 a4 = *(const float4*)(arow + k0 + kk);
        float4 b4 = *(const float4*)(brow + k0 + kk);
        __syncthreads();
        As[kk+0][r] = a4.x; As[kk+1][r] = a4.y; As[kk+2][r] = a4.z; As[kk+3][r] = a4.w;
        Bs[kk+0][r] = b4.x; Bs[kk+1][r] = b4.y; Bs[kk+2][r] = b4.z; Bs[kk+3][r] = b4.w;
        __syncthreads();
        #pragma unroll
        for (int k = 0; k < BK; k++) {
            float4 a0 = *(const float4*)&As[k][ry0];
            float4 a1 = *(const float4*)&As[k][ry1];
            float4 b0 = *(const float4*)&Bs[k][cx0];
            float4 b1 = *(const float4*)&Bs[k][cx1];
            float av[8] = {a0.x,a0.y,a0.z,a0.w,a1.x,a1.y,a1.z,a1.w};
            float bv[8] = {b0.x,b0.y,b0.z,b0.w,b1.x,b1.y,b1.z,b1.w};
            #pragma unroll
            for (int i = 0; i < 8; i++)
                #pragma unroll
                for (int j = 0; j < 8; j++)
                    acc[i][j] = fmaf(av[i], bv[j], acc[i][j]);
        }
    }

    // epilogue: bias + swiglu on (g,v) pairs, store to g_H
    const float* b1e = d1b + (size_t)e * TWO_F;
    float4 bias0 = *(const float4*)(b1e + n0 + cx0);
    float4 bias1 = *(const float4*)(b1e + n0 + cx1);
    int fbase = (n0 >> 1) + tx * 2;
    #pragma unroll
    for (int i = 0; i < 8; i++) {
        int rl = (i < 4) ? (ry0 + i) : (ry1 + i - 4);
        if (rl >= mrows) continue;
        float* Hrow = g_H + (size_t)(row0 + rl) * F_DIM;
        float2 h0, h1;
        h0.x = act_swiglu(acc[i][0] + bias0.x, acc[i][1] + bias0.y);
        h0.y = act_swiglu(acc[i][2] + bias0.z, acc[i][3] + bias0.w);
        h1.x = act_swiglu(acc[i][4] + bias1.x, acc[i][5] + bias1.y);
        h1.y = act_swiglu(acc[i][6] + bias1.z, acc[i][7] + bias1.w);
        *(float2*)(Hrow + fbase)      = h0;
        *(float2*)(Hrow + fbase + 32) = h1;
    }
}

// ---------------- kernel 5: y = H @ d2w[e]^T + b2 ; out += w * y -----------
// C[p][d] = sum_f H[p][f] * d2w[e][d][f]
__global__ __launch_bounds__(256)
void gemm2_kernel(const float* __restrict__ d2w,
                  const float* __restrict__ d2b,
                  float* __restrict__ out) {
    int tile = blockIdx.y;
    if (tile >= g_num_tiles) return;
    int e     = g_tile_expert[tile];
    int row0  = g_tile_row0[tile];
    int mrows = g_tile_m[tile];
    int n0    = blockIdx.x * BN;

    __shared__ float As[BK][SSTRIDE];
    __shared__ float Bs[BK][SSTRIDE];

    int tid = threadIdx.x;
    int r   = tid >> 1;
    int kk  = (tid & 1) * 4;

    int ra = (r < mrows) ? r : 0;
    const float* arow = g_H + (size_t)(row0 + ra) * F_DIM;
    const float* brow = d2w + ((size_t)e * D_DIM + (n0 + r)) * F_DIM;

    int tx = tid & 15, ty = tid >> 4;
    int ry0 = ty * 4, ry1 = ty * 4 + 64;
    int cx0 = tx * 4, cx1 = tx * 4 + 64;

    float acc[8][8];
    #pragma unroll
    for (int i = 0; i < 8; i++)
        #pragma unroll
        for (int j = 0; j < 8; j++) acc[i][j] = 0.0f;

    for (int k0 = 0; k0 < F_DIM; k0 += BK) {
        float4 a4 = *(const float4*)(arow + k0 + kk);
        float4 b4 = *(const float4*)(brow + k0 + kk);
        __syncthreads();
        As[kk+0][r] = a4.x; As[kk+1][r] = a4.y; As[kk+2][r] = a4.z; As[kk+3][r] = a4.w;
        Bs[kk+0][r] = b4.x; Bs[kk+1][r] = b4.y; Bs[kk+2][r] = b4.z; Bs[kk+3][r] = b4.w;
        __syncthreads();
        #pragma unroll
        for (int k = 0; k < BK; k++) {
            float4 a0 = *(const float4*)&As[k][ry0];
            float4 a1 = *(const float4*)&As[k][ry1];
            float4 b0 = *(const float4*)&Bs[k][cx0];
            float4 b1 = *(const float4*)&Bs[k][cx1];
            float av[8] = {a0.x,a0.y,a0.z,a0.w,a1.x,a1.y,a1.z,a1.w};
            float bv[8] = {b0.x,b0.y,b0.z,b0.w,b1.x,b1.y,b1.z,b1.w};
            #pragma unroll
            for (int i = 0; i < 8; i++)
                #pragma unroll
                for (int j = 0; j < 8; j++)
                    acc[i][j] = fmaf(av[i], bv[j], acc[i][j]);
        }
    }

    // epilogue: bias, weight, atomic scatter-add into out[token]
    const float* b2e = d2b + (size_t)e * D_DIM;
    float4 bias0 = *(const float4*)(b2e + n0 + cx0);
    float4 bias1 = *(const float4*)(b2e + n0 + cx1);
    float bv0[8] = {bias0.x,bias0.y,bias0.z,bias0.w,bias1.x,bias1.y,bias1.z,bias1.w};
    #pragma unroll
    for (int i = 0; i < 8; i++) {
        int rl = (i < 4) ? (ry0 + i) : (ry1 + i - 4);
        if (rl >= mrows) continue;
        int p = row0 + rl;
        int tok   = g_pair_tok[p];
        float wgt = g_pair_w[p];
        float* orow = out + (size_t)tok * D_DIM;
        #pragma unroll
        for (int j = 0; j < 8; j++) {
            int d = n0 + ((j < 4) ? (cx0 + j) : (cx1 + j - 4));
            atomicAdd(orow + d, wgt * (acc[i][j] + bv0[j]));
        }
    }
}

// ---------------- launch ----------------
extern "C" void kernel_launch(void* const* d_in, const int* in_sizes, int n_in,
                              void* d_out, int out_size) {
    const float* x   = (const float*)d_in[0];
    const float* gw  = (const float*)d_in[1];
    const float* d1w = (const float*)d_in[2];
    const float* d1b = (const float*)d_in[3];
    const float* d2w = (const float*)d_in[4];
    const float* d2b = (const float*)d_in[5];
    float* out = (float*)d_out;

    int T = in_sizes[0] / D_DIM;   // 4096

    cudaMemsetAsync(d_out, 0, (size_t)out_size * sizeof(float));
    init_kernel<<<1, 32>>>();
    gate_kernel<<<(T + 7) / 8, 256>>>(x, gw, T);
    setup_kernel<<<1, 32>>>();
    scatter_kernel<<<(T + 255) / 256, 256>>>(T);

    dim3 grid1(TWO_F / BN, MAX_TILES);   // (32, 96)
    gemm1_kernel<<<grid1, 256>>>(x, d1w, d1b);

    dim3 grid2(D_DIM / BN, MAX_TILES);   // (8, 96)
    gemm2_kernel<<<grid2, 256>>>(d2w, d2b, out);
}

// round 17
// speedup vs baseline: 1.0015x; 1.0004x over previous
#include <cuda_runtime.h>
#include <cuda_bf16.h>
#include <math.h>

// ---------------- problem constants ----------------
#define T_MAX   4096          // B*L tokens
#define D_DIM   1024
#define E_NUM   8
#define F_DIM   2048
#define TWO_F   4096
#define NP      (T_MAX * 2)   // total (token, k) pairs, always exactly 2*T

#define BM 128
#define BN 128
#define BK 8
#define SSTRIDE 132           // padded smem row stride (multiple of 4, bank-rotating)
#define MAX_TILES 96

// ---------------- device scratch (static, no allocations) ----------------
__device__ int    g_cnt[E_NUM];
__device__ int    g_cursor[E_NUM];
__device__ int    g_off[E_NUM + 1];
__device__ int    g_num_tiles;
__device__ int    g_tile_expert[MAX_TILES];
__device__ int    g_tile_row0[MAX_TILES];
__device__ int    g_tile_m[MAX_TILES];
__device__ int2   g_sel[T_MAX];
__device__ float2 g_wts[T_MAX];
__device__ int    g_pair_tok[NP];
__device__ float  g_pair_w[NP];
__device__ float  g_H[(size_t)NP * F_DIM];   // 64 MiB activation scratch

// ---------------- helpers ----------------
__device__ __forceinline__ float act_swiglu(float g, float v) {
    g = fminf(g, 9.0f);
    v = fminf(fmaxf(v, -9.0f), 9.0f);
    float s = 1.0f / (1.0f + expf(-1.702f * g));
    return g * s * (v + 1.0f);
}

// ---------------- kernel 0: reset counters ----------------
__global__ void init_kernel() {
    int i = threadIdx.x;
    if (i < E_NUM) { g_cnt[i] = 0; g_cursor[i] = 0; }
}

// ---------------- kernel 1: gate = x @ gate_w, top2, softmax ----------------
// one warp per token
__global__ void gate_kernel(const float* __restrict__ x,
                            const float* __restrict__ gw, int T) {
    int gwarp = (blockIdx.x * blockDim.x + threadIdx.x) >> 5;
    int lane  = threadIdx.x & 31;
    if (gwarp >= T) return;
    const float* xr = x + (size_t)gwarp * D_DIM;

    float acc[8] = {0,0,0,0,0,0,0,0};
    for (int d = lane; d < D_DIM; d += 32) {
        float xv = xr[d];
        float4 w0 = *(const float4*)(gw + (size_t)d * E_NUM);
        float4 w1 = *(const float4*)(gw + (size_t)d * E_NUM + 4);
        acc[0] = fmaf(xv, w0.x, acc[0]);
        acc[1] = fmaf(xv, w0.y, acc[1]);
        acc[2] = fmaf(xv, w0.z, acc[2]);
        acc[3] = fmaf(xv, w0.w, acc[3]);
        acc[4] = fmaf(xv, w1.x, acc[4]);
        acc[5] = fmaf(xv, w1.y, acc[5]);
        acc[6] = fmaf(xv, w1.z, acc[6]);
        acc[7] = fmaf(xv, w1.w, acc[7]);
    }
    #pragma unroll
    for (int e = 0; e < 8; e++) {
        #pragma unroll
        for (int o = 16; o > 0; o >>= 1)
            acc[e] += __shfl_xor_sync(0xFFFFFFFFu, acc[e], o);
    }
    if (lane == 0) {
        float v0 = -INFINITY, v1 = -INFINITY;
        int   i0 = 0,          i1 = 0;
        #pragma unroll
        for (int e = 0; e < 8; e++) {
            float v = acc[e];
            if (v > v0)      { v1 = v0; i1 = i0; v0 = v; i0 = e; }
            else if (v > v1) { v1 = v;  i1 = e; }
        }
        // softmax over {v0, v1}; v0 is the max
        float e1 = expf(v1 - v0);
        float inv = 1.0f / (1.0f + e1);
        g_sel[gwarp] = make_int2(i0, i1);
        g_wts[gwarp] = make_float2(inv, e1 * inv);
        atomicAdd(&g_cnt[i0], 1);
        atomicAdd(&g_cnt[i1], 1);
    }
}

// ---------------- kernel 2: prefix offsets + tile map ----------------
__global__ void setup_kernel() {
    if (threadIdx.x == 0 && blockIdx.x == 0) {
        int off = 0, nt = 0;
        for (int e = 0; e < E_NUM; e++) {
            g_off[e] = off;
            int c = g_cnt[e];
            for (int m = 0; m < c; m += BM) {
                g_tile_expert[nt] = e;
                g_tile_row0[nt]   = off + m;
                g_tile_m[nt]      = min(BM, c - m);
                nt++;
            }
            off += c;
        }
        g_off[E_NUM] = off;
        g_num_tiles  = nt;
    }
}

// ---------------- kernel 3: scatter tokens into expert-sorted pair list ----
__global__ void scatter_kernel(int T) {
    int t = blockIdx.x * blockDim.x + threadIdx.x;
    if (t >= T) return;
    int2   sel = g_sel[t];
    float2 w   = g_wts[t];
    int p0 = g_off[sel.x] + atomicAdd(&g_cursor[sel.x], 1);
    g_pair_tok[p0] = t;  g_pair_w[p0] = w.x;
    int p1 = g_off[sel.y] + atomicAdd(&g_cursor[sel.y], 1);
    g_pair_tok[p1] = t;  g_pair_w[p1] = w.y;
}

// ---------------- kernel 4: H = swiglu(x_gathered @ d1w[e]^T + b1) ----------
// C[p][c] = sum_d x[tok(p)][d] * d1w[e][c][d]   (both K-major -> A*B^T)
__global__ __launch_bounds__(256)
void gemm1_kernel(const float* __restrict__ x,
                  const float* __restrict__ d1w,
                  const float* __restrict__ d1b) {
    int tile = blockIdx.y;
    if (tile >= g_num_tiles) return;
    int e     = g_tile_expert[tile];
    int row0  = g_tile_row0[tile];
    int mrows = g_tile_m[tile];
    int n0    = blockIdx.x * BN;

    __shared__ float As[BK][SSTRIDE];
    __shared__ float Bs[BK][SSTRIDE];

    int tid = threadIdx.x;
    int r   = tid >> 1;          // 0..127
    int kk  = (tid & 1) * 4;     // 0 or 4

    int tokr = g_pair_tok[row0 + ((r < mrows) ? r : 0)];
    const float* arow = x   + (size_t)tokr * D_DIM;
    const float* brow = d1w + ((size_t)e * TWO_F + (n0 + r)) * D_DIM;

    int tx = tid & 15, ty = tid >> 4;
    int ry0 = ty * 4, ry1 = ty * 4 + 64;
    int cx0 = tx * 4, cx1 = tx * 4 + 64;

    float acc[8][8];
    #pragma unroll
    for (int i = 0; i < 8; i++)
        #pragma unroll
        for (int j = 0; j < 8; j++) acc[i][j] = 0.0f;

    for (int k0 = 0; k0 < D_DIM; k0 += BK) {
        float4 a4 = *(const float4*)(arow + k0 + kk);
        float4 b4 = *(const float4*)(brow + k0 + kk);
        __syncthreads();
        As[kk+0][r] = a4.x; As[kk+1][r] = a4.y; As[kk+2][r] = a4.z; As[kk+3][r] = a4.w;
        Bs[kk+0][r] = b4.x; Bs[kk+1][r] = b4.y; Bs[kk+2][r] = b4.z; Bs[kk+3][r] = b4.w;
        __syncthreads();
        #pragma unroll
        for (int k = 0; k < BK; k++) {
            float4 a0 = *(const float4*)&As[k][ry0];
            float4 a1 = *(const float4*)&As[k][ry1];
            float4 b0 = *(const float4*)&Bs[k][cx0];
            float4 b1 = *(const float4*)&Bs[k][cx1];
            float av[8] = {a0.x,a0.y,a0.z,a0.w,a1.x,a1.y,a1.z,a1.w};
            float bv[8] = {b0.x,b0.y,b0.z,b0.w,b1.x,b1.y,b1.z,b1.w};
            #pragma unroll
            for (int i = 0; i < 8; i++)
                #pragma unroll
                for (int j = 0; j < 8; j++)
                    acc[i][j] = fmaf(av[i], bv[j], acc[i][j]);
        }
    }

    // epilogue: bias + swiglu on (g,v) pairs, store to g_H
    const float* b1e = d1b + (size_t)e * TWO_F;
    float4 bias0 = *(const float4*)(b1e + n0 + cx0);
    float4 bias1 = *(const float4*)(b1e + n0 + cx1);
    int fbase = (n0 >> 1) + tx * 2;
    #pragma unroll
    for (int i = 0; i < 8; i++) {
        int rl = (i < 4) ? (ry0 + i) : (ry1 + i - 4);
        if (rl >= mrows) continue;
        float* Hrow = g_H + (size_t)(row0 + rl) * F_DIM;
        float2 h0, h1;
        h0.x = act_swiglu(acc[i][0] + bias0.x, acc[i][1] + bias0.y);
        h0.y = act_swiglu(acc[i][2] + bias0.z, acc[i][3] + bias0.w);
        h1.x = act_swiglu(acc[i][4] + bias1.x, acc[i][5] + bias1.y);
        h1.y = act_swiglu(acc[i][6] + bias1.z, acc[i][7] + bias1.w);
        *(float2*)(Hrow + fbase)      = h0;
        *(float2*)(Hrow + fbase + 32) = h1;
    }
}

// ---------------- kernel 5: y = H @ d2w[e]^T + b2 ; out += w * y -----------
// C[p][d] = sum_f H[p][f] * d2w[e][d][f]
__global__ __launch_bounds__(256)
void gemm2_kernel(const float* __restrict__ d2w,
                  const float* __restrict__ d2b,
                  float* __restrict__ out) {
    int tile = blockIdx.y;
    if (tile >= g_num_tiles) return;
    int e     = g_tile_expert[tile];
    int row0  = g_tile_row0[tile];
    int mrows = g_tile_m[tile];
    int n0    = blockIdx.x * BN;

    __shared__ float As[BK][SSTRIDE];
    __shared__ float Bs[BK][SSTRIDE];

    int tid = threadIdx.x;
    int r   = tid >> 1;
    int kk  = (tid & 1) * 4;

    int ra = (r < mrows) ? r : 0;
    const float* arow = g_H + (size_t)(row0 + ra) * F_DIM;
    const float* brow = d2w + ((size_t)e * D_DIM + (n0 + r)) * F_DIM;

    int tx = tid & 15, ty = tid >> 4;
    int ry0 = ty * 4, ry1 = ty * 4 + 64;
    int cx0 = tx * 4, cx1 = tx * 4 + 64;

    float acc[8][8];
    #pragma unroll
    for (int i = 0; i < 8; i++)
        #pragma unroll
        for (int j = 0; j < 8; j++) acc[i][j] = 0.0f;

    for (int k0 = 0; k0 < F_DIM; k0 += BK) {
        float4 a4 = *(const float4*)(arow + k0 + kk);
        float4 b4 = *(const float4*)(brow + k0 + kk);
        __syncthreads();
        As[kk+0][r] = a4.x; As[kk+1][r] = a4.y; As[kk+2][r] = a4.z; As[kk+3][r] = a4.w;
        Bs[kk+0][r] = b4.x; Bs[kk+1][r] = b4.y; Bs[kk+2][r] = b4.z; Bs[kk+3][r] = b4.w;
        __syncthreads();
        #pragma unroll
        for (int k = 0; k < BK; k++) {
            float4 a0 = *(const float4*)&As[k][ry0];
            float4 a1 = *(const float4*)&As[k][ry1];
            float4 b0 = *(const float4*)&Bs[k][cx0];
            float4 b1 = *(const float4*)&Bs[k][cx1];
            float av[8] = {a0.x,a0.y,a0.z,a0.w,a1.x,a1.y,a1.z,a1.w};
            float bv[8] = {b0.x,b0.y,b0.z,b0.w,b1.x,b1.y,b1.z,b1.w};
            #pragma unroll
            for (int i = 0; i < 8; i++)
                #pragma unroll
                for (int j = 0; j < 8; j++)
                    acc[i][j] = fmaf(av[i], bv[j], acc[i][j]);
        }
    }

    // epilogue: bias, weight, atomic scatter-add into out[token]
    const float* b2e = d2b + (size_t)e * D_DIM;
    float4 bias0 = *(const float4*)(b2e + n0 + cx0);
    float4 bias1 = *(const float4*)(b2e + n0 + cx1);
    float bv0[8] = {bias0.x,bias0.y,bias0.z,bias0.w,bias1.x,bias1.y,bias1.z,bias1.w};
    #pragma unroll
    for (int i = 0; i < 8; i++) {
        int rl = (i < 4) ? (ry0 + i) : (ry1 + i - 4);
        if (rl >= mrows) continue;
        int p = row0 + rl;
        int tok   = g_pair_tok[p];
        float wgt = g_pair_w[p];
        float* orow = out + (size_t)tok * D_DIM;
        #pragma unroll
        for (int j = 0; j < 8; j++) {
            int d = n0 + ((j < 4) ? (cx0 + j) : (cx1 + j - 4));
            atomicAdd(orow + d, wgt * (acc[i][j] + bv0[j]));
        }
    }
}

// ---------------- launch ----------------
extern "C" void kernel_launch(void* const* d_in, const int* in_sizes, int n_in,
                              void* d_out, int out_size) {
    const float* x   = (const float*)d_in[0];
    const float* gw  = (const float*)d_in[1];
    const float* d1w = (const float*)d_in[2];
    const float* d1b = (const float*)d_in[3];
    const float* d2w = (const float*)d_in[4];
    const float* d2b = (const float*)d_in[5];
    float* out = (float*)d_out;

    int T = in_sizes[0] / D_DIM;   // 4096

    cudaMemsetAsync(d_out, 0, (size_t)out_size * sizeof(float));
    init_kernel<<<1, 32>>>();
    gate_kernel<<<(T + 7) / 8, 256>>>(x, gw, T);
    setup_kernel<<<1, 32>>>();
    scatter_kernel<<<(T + 255) / 256, 256>>>(T);

    dim3 grid1(TWO_F / BN, MAX_TILES);   // (32, 96)
    gemm1_kernel<<<grid1, 256>>>(x, d1w, d1b);

    dim3 grid2(D_DIM / BN, MAX_TILES);   // (8, 96)
    gemm2_kernel<<<grid2, 256>>>(d2w, d2b, out);
}